// round 4
// baseline (speedup 1.0000x reference)
#include <cuda_runtime.h>
#include <cuda_fp16.h>
#include <math.h>

// Problem dims
#define T_LEN 512
#define M_    4
#define N_    48
#define DIN   52          // M + N
#define H1_   4160
#define HID_  2320
#define G3_   6960        // 3 * HID
#define H2_   768
#define DOUT  192         // M * N

#define NBLK  148
#define NTHR  512
#define NWARP 16

// roles
#define SLAB_B0 3
#define NSLAB   145       // blocks 3..147 own 16 GRU units each (145*16 = 2320)
#define UNITS   16
#define W3_B0   3
#define W3_NB   8         // blocks 3..10 also do W3 (24 rows each)
#define SEGW    2080      // j-range per W1 block (blocks 1,2)
#define JCH_HH  (HID_ / NWARP)   // 145 columns per warp in Whh axpy

// ---------------- device scratch (static: allocation-free) ----------------
__device__ __align__(16) __half w_ihT[(size_t)H1_ * G3_];   // [j][g*HID+i] 57.9MB
__device__ __align__(16) __half w_hhT[(size_t)HID_ * G3_];  // [j][g*HID+i] 32.3MB
__device__ __align__(16) __half w2_h[(size_t)H2_ * HID_];   // row-major   3.6MB

__device__ __align__(16) float    g_h[HID_];      // hidden state fp32
__device__ __align__(16) float    g_l2[H2_];
__device__ __align__(16) float    g_z[DOUT];
__device__ __align__(16) float    g_knet[DIN + 4];
__device__ __align__(16) unsigned g_pairs[2 * SEGW];  // (j<<16)|half(l1)
__device__ unsigned g_cnt[2];
__device__ unsigned g_bar_count;
__device__ unsigned g_bar_gen;
__device__ unsigned g_knet_flag;
__device__ unsigned g_l2done;
__device__ unsigned g_zdone;

// ---------------- conversion / transpose kernels ---------------------------
// dst[j*R + r] = half(src[r*C + j])   (R rows, C cols in src)
__global__ void transpose_cvt(const float* __restrict__ src,
                              __half* __restrict__ dst, int R, int C) {
    __shared__ float tile[32][33];
    int j0 = blockIdx.x * 32, r0 = blockIdx.y * 32;
    int tx = threadIdx.x, ty = threadIdx.y;   // 32 x 8
    for (int d = ty; d < 32; d += 8) {
        int r = r0 + d, j = j0 + tx;
        tile[d][tx] = (r < R && j < C) ? src[(size_t)r * C + j] : 0.f;
    }
    __syncthreads();
    for (int d = ty; d < 32; d += 8) {
        int j = j0 + d, r = r0 + tx;
        if (j < C && r < R) dst[(size_t)j * R + r] = __float2half(tile[tx][d]);
    }
}

__global__ void cvt_w2(const float* __restrict__ W2) {
    size_t i0 = (size_t)blockIdx.x * blockDim.x + threadIdx.x;
    size_t st = (size_t)gridDim.x * blockDim.x;
    const size_t n = (size_t)H2_ * HID_ / 8;
    for (size_t g = i0; g < n; g += st) {
        const float4* s4 = (const float4*)W2;
        float4 a = s4[2 * g], b = s4[2 * g + 1];
        __half2 h0 = __floats2half2_rn(a.x, a.y);
        __half2 h1 = __floats2half2_rn(a.z, a.w);
        __half2 h2 = __floats2half2_rn(b.x, b.y);
        __half2 h3 = __floats2half2_rn(b.z, b.w);
        uint4 o;
        o.x = *(unsigned*)&h0; o.y = *(unsigned*)&h1;
        o.z = *(unsigned*)&h2; o.w = *(unsigned*)&h3;
        ((uint4*)w2_h)[g] = o;
    }
}

// ---------------- grid barrier --------------------------------------------
__device__ __forceinline__ void grid_barrier() {
    __threadfence();
    __syncthreads();
    if (threadIdx.x == 0) {
        unsigned gen = *((volatile unsigned*)&g_bar_gen);
        if (atomicAdd(&g_bar_count, 1u) == gridDim.x - 1u) {
            atomicExch(&g_bar_count, 0u);
            __threadfence();
            *((volatile unsigned*)&g_bar_gen) = gen + 1u;
        } else {
            while (*((volatile unsigned*)&g_bar_gen) == gen) { }
        }
        __threadfence();
    }
    __syncthreads();
}

// ---------------- dots ------------------------------------------------------
// half row x fp32 smem vector, fp32 accum (for W2 rows)
__device__ __forceinline__ float dot_h_row(const __half* __restrict__ w,
                                           const float* __restrict__ x) {
    const uint4* w4 = (const uint4*)w;
    const float4* x4 = (const float4*)x;
    int lane = threadIdx.x & 31;
    float a0 = 0.f, a1 = 0.f, a2 = 0.f, a3 = 0.f;
#pragma unroll 4
    for (int c = lane; c < HID_ / 8; c += 32) {
        uint4 wv = w4[c];
        float4 xa = x4[2 * c], xb = x4[2 * c + 1];
        float2 f;
        f = __half22float2(*(__half2*)&wv.x); a0 = fmaf(f.x, xa.x, a0); a1 = fmaf(f.y, xa.y, a1);
        f = __half22float2(*(__half2*)&wv.y); a2 = fmaf(f.x, xa.z, a2); a3 = fmaf(f.y, xa.w, a3);
        f = __half22float2(*(__half2*)&wv.z); a0 = fmaf(f.x, xb.x, a0); a1 = fmaf(f.y, xb.y, a1);
        f = __half22float2(*(__half2*)&wv.w); a2 = fmaf(f.x, xb.z, a2); a3 = fmaf(f.y, xb.w, a3);
    }
    float acc = (a0 + a1) + (a2 + a3);
#pragma unroll
    for (int o = 16; o; o >>= 1) acc += __shfl_down_sync(0xffffffffu, acc, o);
    return acc;
}

// fp32 row dot over H2 (for W3)
__device__ __forceinline__ float warp_dot_f(const float* __restrict__ w,
                                            const float* __restrict__ x) {
    const float4* w4 = (const float4*)w;
    const float4* x4 = (const float4*)x;
    int lane = threadIdx.x & 31;
    float a0 = 0.f, a1 = 0.f, a2 = 0.f, a3 = 0.f;
#pragma unroll
    for (int c = lane; c < H2_ / 4; c += 32) {
        float4 a = w4[c], b = x4[c];
        a0 = fmaf(a.x, b.x, a0); a1 = fmaf(a.y, b.y, a1);
        a2 = fmaf(a.z, b.z, a2); a3 = fmaf(a.w, b.w, a3);
    }
    float acc = (a0 + a1) + (a2 + a3);
#pragma unroll
    for (int o = 16; o; o >>= 1) acc += __shfl_down_sync(0xffffffffu, acc, o);
    return acc;
}

__device__ __forceinline__ float sigmoidf_(float x) {
    return 1.f / (1.f + __expf(-x));
}

// ---------------- persistent kernel ---------------------------------------
__global__ void __launch_bounds__(NTHR, 1)
kalmannet_kernel(const float* __restrict__ A,   const float* __restrict__ C,
                 const float* __restrict__ x0,  const float* __restrict__ h0,
                 const float* __restrict__ y,   const float* __restrict__ W1,
                 const float* __restrict__ b1,  const float* __restrict__ bih,
                 const float* __restrict__ bhh, const float* __restrict__ b2,
                 const float* __restrict__ W3,  const float* __restrict__ b3,
                 float* __restrict__ out) {
    const int tid  = threadIdx.x;
    const int bid  = blockIdx.x;
    const int wid  = tid >> 5;
    const int lane = tid & 31;

    __shared__ __align__(16) float    s_h[HID_];            // h(t-1), fp32
    __shared__ __align__(16) unsigned s_pairs[2 * SEGW];    // phase B / W1 scratch
    __shared__ __align__(16) float    s_part[NWARP * 48];
    __shared__ __align__(16) float    s_gh[48], s_gi[48];
    __shared__ __align__(16) float    s_l2f[H2_];
    __shared__ __align__(16) float    s_z[DOUT];
    __shared__ __align__(16) float    s_knet[56];
    __shared__ float s_dy[N_];
    __shared__ float s_xprior[M_], s_xpost[M_], s_xprev[M_];
    __shared__ unsigned s_wcnt[NWARP], s_woff[NWARP + 1];

    const bool is_slab = (bid >= SLAB_B0);
    const int  sb      = bid - SLAB_B0;          // slab index
    const int  u0      = sb * UNITS;             // first owned unit
    // axpy lane mapping: lanes 0..23, gate = l>>3, pair = l&7
    const int  gidx    = lane >> 3;
    const int  pidx    = lane & 7;
    const int  axoff   = gidx * HID_ + u0 + 2 * pidx;   // half index in a column

    for (int t = 0; t < T_LEN; ++t) {
        // ======================= Phase A =======================
        if (is_slab) {
            // stage h(t-1) fp32
            const float* hsrc = (t == 0) ? h0 : g_h;
            for (int i = tid; i < HID_; i += NTHR) s_h[i] = hsrc[i];
            __syncthreads();

            // ---- W2 rows first (t>0): r = sb + 145*wid, wid<6 ----
            if (t > 0) {
                if (wid < 6) {
                    int r = sb + NSLAB * wid;
                    if (r < H2_) {
                        float v = dot_h_row(w2_h + (size_t)r * HID_, s_h);
                        if (lane == 0) g_l2[r] = fmaxf(v + b2[r], 0.f);
                    }
                }
                __threadfence();
                __syncthreads();
                if (tid == 0) atomicAdd(&g_l2done, 1u);
            }

            // ---- W3 blocks: wait l2, compute z ----
            if (t > 0 && bid >= W3_B0 && bid < W3_B0 + W3_NB) {
                if (tid == 0) {
                    while (*((volatile unsigned*)&g_l2done) != (unsigned)NSLAB) { }
                    __threadfence();
                }
                __syncthreads();
                for (int i = tid; i < H2_; i += NTHR) s_l2f[i] = g_l2[i];
                __syncthreads();
                int rb = (bid - W3_B0) * (DOUT / W3_NB);   // 24 rows
                for (int r = rb + wid; r < rb + DOUT / W3_NB; r += NWARP) {
                    float v = warp_dot_f(W3 + (size_t)r * H2_, s_l2f);
                    if (lane == 0) g_z[r] = (v + b3[r]) * 1e-4f;
                }
                __threadfence();
                __syncthreads();
                if (tid == 0) atomicAdd(&g_zdone, 1u);
            }

            // ---- dense axpy: gh partials for owned 48 rows ----
            {
                float f0 = 0.f, f1 = 0.f;
                if (lane < 24) {
                    const __half* base = w_hhT + axoff;
                    int j0 = wid * JCH_HH;
#pragma unroll 4
                    for (int j = j0; j < j0 + JCH_HH; ++j) {
                        float hx = s_h[j];
                        __half2 w = *(const __half2*)(base + (size_t)j * G3_);
                        float2 wf = __half22float2(w);
                        f0 = fmaf(wf.x, hx, f0);
                        f1 = fmaf(wf.y, hx, f1);
                    }
                    s_part[wid * 48 + gidx * 16 + 2 * pidx]     = f0;
                    s_part[wid * 48 + gidx * 16 + 2 * pidx + 1] = f1;
                }
                __syncthreads();
                if (tid < 48) {
                    float s = 0.f;
#pragma unroll
                    for (int w = 0; w < NWARP; ++w) s += s_part[w * 48 + tid];
                    int g = tid >> 4, u = tid & 15;
                    s_gh[tid] = s + bhh[g * HID_ + u0 + u];
                }
            }
        } else if (bid == 0) {
            // ---- serial chain ----
            if (t == 0) {
                if (tid < M_) { s_xpost[tid] = x0[tid]; s_xprev[tid] = x0[tid]; }
                __syncthreads();
            } else {
                if (tid == 0) {
                    while (*((volatile unsigned*)&g_zdone) != (unsigned)W3_NB) { }
                    __threadfence();
                }
                __syncthreads();
                if (tid < DOUT) s_z[tid] = g_z[tid];
                __syncthreads();
                if (tid < M_) {
                    float acc = 0.f;
#pragma unroll 4
                    for (int j = 0; j < N_; ++j)
                        acc = fmaf(s_z[tid * N_ + j], s_dy[j], acc);
                    float xp = s_xprior[tid] + acc;
                    s_xprev[tid] = s_xprior[tid];
                    s_xpost[tid] = xp;
                    out[tid * T_LEN + (t - 1)] = xp;
                }
                __syncthreads();
            }
            if (tid < M_) {
                float acc = 0.f;
#pragma unroll
                for (int k = 0; k < M_; ++k) acc = fmaf(A[tid * M_ + k], s_xpost[k], acc);
                s_xprior[tid] = acc;
            }
            __syncthreads();
            if (wid == 0) {
                for (int j = lane; j < N_; j += 32) {
                    float m = C[j * (M_ + 1) + M_];
#pragma unroll
                    for (int k = 0; k < M_; ++k) m = fmaf(C[j * (M_ + 1) + k], s_xprior[k], m);
                    s_dy[j] = y[j * T_LEN + t] - m;
                }
                __syncwarp();
                float sq = 0.f;
                for (int j = lane; j < N_; j += 32) sq += s_dy[j] * s_dy[j];
#pragma unroll
                for (int o = 16; o; o >>= 1) sq += __shfl_down_sync(0xffffffffu, sq, o);
                sq = __shfl_sync(0xffffffffu, sq, 0);
                float inv = 1.f / fmaxf(sqrtf(sq), 1e-12f);
                for (int j = lane; j < N_; j += 32) g_knet[j] = s_dy[j] * inv;

                float dx = (lane < M_) ? (s_xpost[lane] - s_xprev[lane]) : 0.f;
                float sq2 = dx * dx;
#pragma unroll
                for (int o = 16; o; o >>= 1) sq2 += __shfl_down_sync(0xffffffffu, sq2, o);
                sq2 = __shfl_sync(0xffffffffu, sq2, 0);
                float inv2 = 1.f / fmaxf(sqrtf(sq2), 1e-12f);
                if (lane < M_) g_knet[N_ + lane] = dx * inv2;
                __syncwarp();
                if (lane == 0) {
                    __threadfence();
                    atomicExch(&g_knet_flag, 1u);
                }
            }
        } else {
            // ---- blocks 1,2: l1 = relu(W1@knet) + deterministic compaction ----
            const int seg = bid - 1;
            if (tid == 0) {
                while (*((volatile unsigned*)&g_knet_flag) == 0u) { }
                __threadfence();
            }
            __syncthreads();
            if (tid < DIN) s_knet[tid] = g_knet[tid];
            __syncthreads();
            {
                const int wj0 = seg * SEGW + wid * (SEGW / NWARP);  // 130 per warp
                unsigned cnt = 0;
#pragma unroll
                for (int it = 0; it < 5; ++it) {
                    int k = it * 32 + lane;
                    float v = 0.f;
                    int j = wj0 + k;
                    bool act = (k < SEGW / NWARP);
                    if (act) {
                        const float4* w4 = (const float4*)(W1 + (size_t)j * DIN);
                        const float4* k4 = (const float4*)s_knet;
                        float acc = b1[j];
#pragma unroll
                        for (int c = 0; c < DIN / 4; ++c) {
                            float4 a = w4[c], b = k4[c];
                            acc = fmaf(a.x, b.x, acc); acc = fmaf(a.y, b.y, acc);
                            acc = fmaf(a.z, b.z, acc); acc = fmaf(a.w, b.w, acc);
                        }
                        v = fmaxf(acc, 0.f);
                    }
                    bool pred = act && (v > 0.f);
                    unsigned mask = __ballot_sync(0xffffffffu, pred);
                    if (pred) {
                        unsigned pos = cnt + __popc(mask & ((1u << lane) - 1u));
                        unsigned hb = (unsigned)__half_as_ushort(__float2half(v));
                        s_pairs[wid * (SEGW / NWARP) + pos] = ((unsigned)j << 16) | hb;
                    }
                    cnt += __popc(mask);
                }
                if (lane == 0) s_wcnt[wid] = cnt;
            }
            __syncthreads();
            if (tid == 0) {
                unsigned off = 0;
                for (int w = 0; w < NWARP; ++w) { s_woff[w] = off; off += s_wcnt[w]; }
                s_woff[NWARP] = off;
                g_cnt[seg] = off;
            }
            __syncthreads();
            {
                unsigned cnt = s_wcnt[wid], off = s_woff[wid];
                for (unsigned k = lane; k < cnt; k += 32)
                    g_pairs[seg * SEGW + off + k] = s_pairs[wid * (SEGW / NWARP) + k];
            }
        }
        grid_barrier();

        // ============ Phase B: sparse Wih axpy + gate ============
        if (bid == 0 && tid == 0) {
            g_knet_flag = 0u; g_l2done = 0u; g_zdone = 0u;
        }
        if (is_slab) {
            unsigned c0 = g_cnt[0], c1 = g_cnt[1];
            for (unsigned k = tid; k < c0; k += NTHR) s_pairs[k] = g_pairs[k];
            for (unsigned k = tid; k < c1; k += NTHR) s_pairs[c0 + k] = g_pairs[SEGW + k];
            __syncthreads();
            const int total = (int)(c0 + c1);
            float f0 = 0.f, f1 = 0.f;
            if (lane < 24) {
                const __half* base = w_ihT + axoff;
#pragma unroll 4
                for (int k = wid; k < total; k += NWARP) {
                    unsigned pr = s_pairs[k];
                    float xv = __half2float(__ushort_as_half((unsigned short)(pr & 0xffffu)));
                    int j = (int)(pr >> 16);
                    __half2 w = *(const __half2*)(base + (size_t)j * G3_);
                    float2 wf = __half22float2(w);
                    f0 = fmaf(wf.x, xv, f0);
                    f1 = fmaf(wf.y, xv, f1);
                }
                s_part[wid * 48 + gidx * 16 + 2 * pidx]     = f0;
                s_part[wid * 48 + gidx * 16 + 2 * pidx + 1] = f1;
            }
            __syncthreads();
            if (tid < 48) {
                float s = 0.f;
#pragma unroll
                for (int w = 0; w < NWARP; ++w) s += s_part[w * 48 + tid];
                int g = tid >> 4, u = tid & 15;
                s_gi[tid] = s + bih[g * HID_ + u0 + u];
            }
            __syncthreads();
            if (tid < UNITS) {
                int i = u0 + tid;
                float rg = sigmoidf_(s_gi[tid]      + s_gh[tid]);
                float zg = sigmoidf_(s_gi[16 + tid] + s_gh[16 + tid]);
                float ng = tanhf(s_gi[32 + tid] + rg * s_gh[32 + tid]);
                g_h[i] = (1.f - zg) * ng + zg * s_h[i];
            }
        }
        grid_barrier();
    }

    // ================= epilogue: final posterior ==========================
    if (is_slab) {
        for (int i = tid; i < HID_; i += NTHR) s_h[i] = g_h[i];
        __syncthreads();
        if (wid < 6) {
            int r = sb + NSLAB * wid;
            if (r < H2_) {
                float v = dot_h_row(w2_h + (size_t)r * HID_, s_h);
                if (lane == 0) g_l2[r] = fmaxf(v + b2[r], 0.f);
            }
        }
        __threadfence();
        __syncthreads();
        if (tid == 0) atomicAdd(&g_l2done, 1u);
        if (bid >= W3_B0 && bid < W3_B0 + W3_NB) {
            if (tid == 0) {
                while (*((volatile unsigned*)&g_l2done) != (unsigned)NSLAB) { }
                __threadfence();
            }
            __syncthreads();
            for (int i = tid; i < H2_; i += NTHR) s_l2f[i] = g_l2[i];
            __syncthreads();
            int rb = (bid - W3_B0) * (DOUT / W3_NB);
            for (int r = rb + wid; r < rb + DOUT / W3_NB; r += NWARP) {
                float v = warp_dot_f(W3 + (size_t)r * H2_, s_l2f);
                if (lane == 0) g_z[r] = (v + b3[r]) * 1e-4f;
            }
            __threadfence();
            __syncthreads();
            if (tid == 0) atomicAdd(&g_zdone, 1u);
        }
    } else if (bid == 0) {
        if (tid == 0) {
            while (*((volatile unsigned*)&g_zdone) != (unsigned)W3_NB) { }
            __threadfence();
        }
        __syncthreads();
        if (tid < DOUT) s_z[tid] = g_z[tid];
        __syncthreads();
        if (tid < M_) {
            float acc = 0.f;
#pragma unroll 4
            for (int j = 0; j < N_; ++j) acc = fmaf(s_z[tid * N_ + j], s_dy[j], acc);
            out[tid * T_LEN + (T_LEN - 1)] = s_xprior[tid] + acc;
        }
        __syncthreads();
        if (tid == 0) { atomicExch(&g_l2done, 0u); atomicExch(&g_zdone, 0u); }
    }
}

// ---------------- launch ---------------------------------------------------
extern "C" void kernel_launch(void* const* d_in, const int* in_sizes, int n_in,
                              void* d_out, int out_size) {
    const float* A    = (const float*)d_in[0];
    const float* C    = (const float*)d_in[1];
    const float* x0   = (const float*)d_in[2];
    const float* h0   = (const float*)d_in[3];
    const float* y    = (const float*)d_in[4];
    const float* W1   = (const float*)d_in[5];
    const float* b1   = (const float*)d_in[6];
    const float* Wih  = (const float*)d_in[7];
    const float* Whh  = (const float*)d_in[8];
    const float* bih  = (const float*)d_in[9];
    const float* bhh  = (const float*)d_in[10];
    const float* W2   = (const float*)d_in[11];
    const float* b2   = (const float*)d_in[12];
    const float* W3   = (const float*)d_in[13];
    const float* b3   = (const float*)d_in[14];
    float* out = (float*)d_out;

    // Wih: G3 x H1 -> w_ihT[j in H1][p in G3]
    {
        __half* dst = nullptr; cudaGetSymbolAddress((void**)&dst, w_ihT);
        dim3 blk(32, 8), grd((H1_ + 31) / 32, (G3_ + 31) / 32);
        transpose_cvt<<<grd, blk>>>(Wih, dst, G3_, H1_);
    }
    // Whh: G3 x HID -> w_hhT[j in HID][p in G3]
    {
        __half* dst = nullptr; cudaGetSymbolAddress((void**)&dst, w_hhT);
        dim3 blk(32, 8), grd((HID_ + 31) / 32, (G3_ + 31) / 32);
        transpose_cvt<<<grd, blk>>>(Whh, dst, G3_, HID_);
    }
    cvt_w2<<<1024, 256>>>(W2);

    kalmannet_kernel<<<NBLK, NTHR>>>(A, C, x0, h0, y, W1, b1, bih, bhh,
                                     b2, W3, b3, out);
}

// round 5
// speedup vs baseline: 1.1328x; 1.1328x over previous
#include <cuda_runtime.h>
#include <cuda_fp16.h>
#include <math.h>

// Problem dims
#define T_LEN 512
#define M_    4
#define N_    48
#define DIN   52
#define H1_   4160
#define HID_  2320
#define G3_   6960
#define H2_   768
#define DOUT  192

#define NBLK  148
#define NTHR  512
#define NWARP 16

// roles
#define W2_LO   1
#define W2_HI   48     // 48 blocks, 16 rows each
#define W3_LO   1
#define W3_HI   16     // 16 blocks, 12 rows each
#define W1_LO   17
#define W1_HI   24     // 8 blocks, 520 rows each
#define WHH_LO  49     // 99 blocks
#define WHH_NB  99
#define WHH_WARPS (WHH_NB * NWARP)   // 1584

// ---------------- device scratch ----------------
__device__ __align__(16) __half w_ihH[(size_t)G3_ * H1_];   // row-major, 57.9MB
__device__ __align__(16) __half w_hhH[(size_t)G3_ * HID_];  // 32.3MB
__device__ __align__(16) __half w2H[(size_t)H2_ * HID_];    // 3.6MB

__device__ __align__(16) float  g_hf[HID_];      // fp32 hidden (hold)
__device__ __align__(16) __half g_hh2[HID_];     // fp16 hidden (matvec)
__device__ __align__(16) __half g_l1h[H1_];      // l1 fp16
__device__ __align__(16) float  g_gh[G3_];
__device__ __align__(16) float  g_l2[H2_];
__device__ __align__(16) float  g_z[DOUT];
__device__ __align__(16) float  g_knet[DIN + 4];
__device__ unsigned g_l2done, g_zdone, g_knetflag, g_l1done, g_ghdone;
__device__ unsigned g_bar_count, g_bar_gen;

// ---------------- conversion kernel ----------------
__device__ __forceinline__ void cvt8(const float* __restrict__ src,
                                     __half* __restrict__ dst, size_t g) {
    const float4* s4 = (const float4*)src;
    float4 a = s4[2 * g], b = s4[2 * g + 1];
    __half2 h0 = __floats2half2_rn(a.x, a.y);
    __half2 h1 = __floats2half2_rn(a.z, a.w);
    __half2 h2 = __floats2half2_rn(b.x, b.y);
    __half2 h3 = __floats2half2_rn(b.z, b.w);
    uint4 o;
    o.x = *(unsigned*)&h0; o.y = *(unsigned*)&h1;
    o.z = *(unsigned*)&h2; o.w = *(unsigned*)&h3;
    ((uint4*)dst)[g] = o;
}

__global__ void cvt_kernel(const float* __restrict__ Wih,
                           const float* __restrict__ Whh,
                           const float* __restrict__ W2) {
    size_t i0 = (size_t)blockIdx.x * blockDim.x + threadIdx.x;
    size_t st = (size_t)gridDim.x * blockDim.x;
    const size_t nIH = (size_t)G3_ * H1_ / 8, nHH = (size_t)G3_ * HID_ / 8;
    const size_t n2 = (size_t)H2_ * HID_ / 8;
    for (size_t g = i0; g < nIH; g += st) cvt8(Wih, w_ihH, g);
    for (size_t g = i0; g < nHH; g += st) cvt8(Whh, w_hhH, g);
    for (size_t g = i0; g < n2;  g += st) cvt8(W2, w2H, g);
}

// ---------------- lightweight grid barrier (tid0-only fence) ---------------
__device__ __forceinline__ void grid_barrier() {
    __syncthreads();
    if (threadIdx.x == 0) {
        __threadfence();   // release (cumulative over block via bar.sync)
        unsigned gen = *((volatile unsigned*)&g_bar_gen);
        if (atomicAdd(&g_bar_count, 1u) == (unsigned)gridDim.x - 1u) {
            *((volatile unsigned*)&g_bar_count) = 0u;
            __threadfence();
            *((volatile unsigned*)&g_bar_gen) = gen + 1u;
        } else {
            while (*((volatile unsigned*)&g_bar_gen) == gen) { }
        }
        __threadfence();   // acquire
    }
    __syncthreads();
}

// producer completion: all threads' stores -> visible, then count
__device__ __forceinline__ void signal_done(unsigned* ctr) {
    __syncthreads();
    if (threadIdx.x == 0) { __threadfence(); atomicAdd(ctr, 1u); }
}
// consumer: spin until ctr >= target
__device__ __forceinline__ void wait_ctr(unsigned* ctr, unsigned target) {
    if (threadIdx.x == 0) {
        while (*((volatile unsigned*)ctr) < target) { }
        __threadfence();
    }
    __syncthreads();
}

#define H2AT(u) (*(const __half2*)&(u))

// ---------------- dots ----------------
// single fp16 row x half2 smem vector
__device__ __forceinline__ float warp_dot_hh(const __half* __restrict__ w,
                                             const uint4* __restrict__ xs,
                                             int n8) {
    const uint4* w4 = (const uint4*)w;
    int lane = threadIdx.x & 31;
    __half2 z = __float2half2_rn(0.f);
    __half2 a0 = z, a1 = z, a2 = z, a3 = z;
#pragma unroll 4
    for (int c = lane; c < n8; c += 32) {
        uint4 wv = w4[c], xv = xs[c];
        a0 = __hfma2(H2AT(wv.x), H2AT(xv.x), a0);
        a1 = __hfma2(H2AT(wv.y), H2AT(xv.y), a1);
        a2 = __hfma2(H2AT(wv.z), H2AT(xv.z), a2);
        a3 = __hfma2(H2AT(wv.w), H2AT(xv.w), a3);
    }
    float2 f0 = __half22float2(a0), f1 = __half22float2(a1);
    float2 f2 = __half22float2(a2), f3 = __half22float2(a3);
    float acc = ((f0.x + f0.y) + (f1.x + f1.y)) + ((f2.x + f2.y) + (f3.x + f3.y));
#pragma unroll
    for (int o = 16; o; o >>= 1) acc += __shfl_down_sync(0xffffffffu, acc, o);
    return acc;
}

// 3 interleaved fp16 rows x half2 smem vector (3 independent LDG streams)
__device__ __forceinline__ float3 dot3_hh(const __half* __restrict__ wa,
                                          const __half* __restrict__ wb,
                                          const __half* __restrict__ wc,
                                          const uint4* __restrict__ xs,
                                          int n8) {
    const uint4* A = (const uint4*)wa;
    const uint4* B = (const uint4*)wb;
    const uint4* Cc = (const uint4*)wc;
    int lane = threadIdx.x & 31;
    __half2 z = __float2half2_rn(0.f);
    __half2 a0 = z, a1 = z, a2 = z, a3 = z;
    __half2 b0 = z, b1 = z, b2 = z, b3 = z;
    __half2 c0 = z, c1 = z, c2 = z, c3 = z;
#pragma unroll 2
    for (int c = lane; c < n8; c += 32) {
        uint4 xv = xs[c];
        uint4 u = A[c], v = B[c], w = Cc[c];
        a0 = __hfma2(H2AT(u.x), H2AT(xv.x), a0);
        a1 = __hfma2(H2AT(u.y), H2AT(xv.y), a1);
        a2 = __hfma2(H2AT(u.z), H2AT(xv.z), a2);
        a3 = __hfma2(H2AT(u.w), H2AT(xv.w), a3);
        b0 = __hfma2(H2AT(v.x), H2AT(xv.x), b0);
        b1 = __hfma2(H2AT(v.y), H2AT(xv.y), b1);
        b2 = __hfma2(H2AT(v.z), H2AT(xv.z), b2);
        b3 = __hfma2(H2AT(v.w), H2AT(xv.w), b3);
        c0 = __hfma2(H2AT(w.x), H2AT(xv.x), c0);
        c1 = __hfma2(H2AT(w.y), H2AT(xv.y), c1);
        c2 = __hfma2(H2AT(w.z), H2AT(xv.z), c2);
        c3 = __hfma2(H2AT(w.w), H2AT(xv.w), c3);
    }
    float2 fa0 = __half22float2(a0), fa1 = __half22float2(a1);
    float2 fa2 = __half22float2(a2), fa3 = __half22float2(a3);
    float2 fb0 = __half22float2(b0), fb1 = __half22float2(b1);
    float2 fb2 = __half22float2(b2), fb3 = __half22float2(b3);
    float2 fc0 = __half22float2(c0), fc1 = __half22float2(c1);
    float2 fc2 = __half22float2(c2), fc3 = __half22float2(c3);
    float ra = ((fa0.x + fa0.y) + (fa1.x + fa1.y)) + ((fa2.x + fa2.y) + (fa3.x + fa3.y));
    float rb = ((fb0.x + fb0.y) + (fb1.x + fb1.y)) + ((fb2.x + fb2.y) + (fb3.x + fb3.y));
    float rc = ((fc0.x + fc0.y) + (fc1.x + fc1.y)) + ((fc2.x + fc2.y) + (fc3.x + fc3.y));
#pragma unroll
    for (int o = 16; o; o >>= 1) {
        ra += __shfl_down_sync(0xffffffffu, ra, o);
        rb += __shfl_down_sync(0xffffffffu, rb, o);
        rc += __shfl_down_sync(0xffffffffu, rc, o);
    }
    return make_float3(ra, rb, rc);
}

// fp32 row dot over H2 (W3)
__device__ __forceinline__ float warp_dot_f(const float* __restrict__ w,
                                            const float* __restrict__ x) {
    const float4* w4 = (const float4*)w;
    const float4* x4 = (const float4*)x;
    int lane = threadIdx.x & 31;
    float a0 = 0.f, a1 = 0.f, a2 = 0.f, a3 = 0.f;
#pragma unroll
    for (int c = lane; c < H2_ / 4; c += 32) {
        float4 a = w4[c], b = x4[c];
        a0 = fmaf(a.x, b.x, a0); a1 = fmaf(a.y, b.y, a1);
        a2 = fmaf(a.z, b.z, a2); a3 = fmaf(a.w, b.w, a3);
    }
    float acc = (a0 + a1) + (a2 + a3);
#pragma unroll
    for (int o = 16; o; o >>= 1) acc += __shfl_down_sync(0xffffffffu, acc, o);
    return acc;
}

__device__ __forceinline__ float sigmoidf_(float x) {
    return 1.f / (1.f + __expf(-x));
}

// ---------------- persistent kernel ----------------
__global__ void __launch_bounds__(NTHR, 1)
kalmannet_kernel(const float* __restrict__ A,   const float* __restrict__ C,
                 const float* __restrict__ x0,  const float* __restrict__ h0,
                 const float* __restrict__ y,   const float* __restrict__ W1,
                 const float* __restrict__ b1,  const float* __restrict__ bih,
                 const float* __restrict__ bhh, const float* __restrict__ b2,
                 const float* __restrict__ W3,  const float* __restrict__ b3,
                 float* __restrict__ out) {
    const int tid  = threadIdx.x;
    const int bid  = blockIdx.x;
    const int wid  = tid >> 5;
    const int lane = tid & 31;

    __shared__ __align__(16) uint4 s_x[H1_ / 8];     // 8320B: h(half2) then l1(half2)
    __shared__ __align__(16) float s_l2f[H2_];
    __shared__ __align__(16) float s_z[DOUT];
    __shared__ __align__(16) float s_knet[56];
    __shared__ __align__(16) float s_gi3[NWARP][4];
    __shared__ float s_dy[N_];
    __shared__ float s_xprior[M_], s_xpost[M_], s_xprev[M_];

    for (int t = 0; t < T_LEN; ++t) {
        // ---------- stage h(t-1) as half2 (blocks that matvec h) ----------
        if ((bid >= W2_LO && bid <= W2_HI && t > 0) || bid >= WHH_LO) {
            if (t == 0) {
                for (int i = tid; i < HID_ / 2; i += NTHR) {
                    float2 f = ((const float2*)h0)[i];
                    ((__half2*)s_x)[i] = __floats2half2_rn(f.x, f.y);
                }
            } else {
                const uint4* src = (const uint4*)g_hh2;
                for (int i = tid; i < HID_ / 8; i += NTHR) s_x[i] = src[i];
            }
            __syncthreads();
        }

        // ---------- W2: l2(t-1) = relu(W2 @ h(t-1) + b2) ----------
        if (bid >= W2_LO && bid <= W2_HI && t > 0) {
            int r = (bid - W2_LO) + 48 * wid;     // 768 rows
            float v = warp_dot_hh(w2H + (size_t)r * HID_, s_x, HID_ / 8);
            if (lane == 0) g_l2[r] = fmaxf(v + b2[r], 0.f);
            signal_done(&g_l2done);
        }

        // ---------- W3: z(t-1) ----------
        if (bid >= W3_LO && bid <= W3_HI && t > 0) {
            wait_ctr(&g_l2done, 48u * (unsigned)t);
            for (int i = tid; i < H2_; i += NTHR) s_l2f[i] = g_l2[i];
            __syncthreads();
            if (wid < 12) {
                int r = (bid - W3_LO) + 16 * wid;  // 192 rows
                float v = warp_dot_f(W3 + (size_t)r * H2_, s_l2f);
                if (lane == 0) g_z[r] = (v + b3[r]) * 1e-4f;
            }
            signal_done(&g_zdone);
        }

        // ---------- block 0: serial chain -> knet ----------
        if (bid == 0) {
            if (t == 0) {
                if (tid < M_) { s_xpost[tid] = x0[tid]; s_xprev[tid] = x0[tid]; }
                __syncthreads();
            } else {
                wait_ctr(&g_zdone, 16u * (unsigned)t);
                if (tid < DOUT) s_z[tid] = g_z[tid];
                __syncthreads();
                if (tid < M_) {
                    float acc = 0.f;
#pragma unroll 4
                    for (int j = 0; j < N_; ++j)
                        acc = fmaf(s_z[tid * N_ + j], s_dy[j], acc);
                    float xp = s_xprior[tid] + acc;
                    s_xprev[tid] = s_xprior[tid];
                    s_xpost[tid] = xp;
                    out[tid * T_LEN + (t - 1)] = xp;
                }
                __syncthreads();
            }
            if (tid < M_) {
                float acc = 0.f;
#pragma unroll
                for (int k = 0; k < M_; ++k) acc = fmaf(A[tid * M_ + k], s_xpost[k], acc);
                s_xprior[tid] = acc;
            }
            __syncthreads();
            if (wid == 0) {
                for (int j = lane; j < N_; j += 32) {
                    float m = C[j * (M_ + 1) + M_];
#pragma unroll
                    for (int k = 0; k < M_; ++k) m = fmaf(C[j * (M_ + 1) + k], s_xprior[k], m);
                    s_dy[j] = y[j * T_LEN + t] - m;
                }
                __syncwarp();
                float sq = 0.f;
                for (int j = lane; j < N_; j += 32) sq += s_dy[j] * s_dy[j];
#pragma unroll
                for (int o = 16; o; o >>= 1) sq += __shfl_down_sync(0xffffffffu, sq, o);
                sq = __shfl_sync(0xffffffffu, sq, 0);
                float inv = 1.f / fmaxf(sqrtf(sq), 1e-12f);
                for (int j = lane; j < N_; j += 32) g_knet[j] = s_dy[j] * inv;

                float dx = (lane < M_) ? (s_xpost[lane] - s_xprev[lane]) : 0.f;
                float sq2 = dx * dx;
#pragma unroll
                for (int o = 16; o; o >>= 1) sq2 += __shfl_down_sync(0xffffffffu, sq2, o);
                sq2 = __shfl_sync(0xffffffffu, sq2, 0);
                float inv2 = 1.f / fmaxf(sqrtf(sq2), 1e-12f);
                if (lane < M_) g_knet[N_ + lane] = dx * inv2;
                __syncwarp();
                if (lane == 0) {
                    __threadfence();
                    *((volatile unsigned*)&g_knetflag) = (unsigned)(t + 1);
                }
            }
        }

        // ---------- W1 blocks: l1 = relu(W1 @ knet + b1) ----------
        if (bid >= W1_LO && bid <= W1_HI) {
            if (tid == 0) {
                while (*((volatile unsigned*)&g_knetflag) < (unsigned)(t + 1)) { }
                __threadfence();
            }
            __syncthreads();
            if (tid < DIN) s_knet[tid] = g_knet[tid];
            __syncthreads();
            int base = (bid - W1_LO) * 520;
#pragma unroll
            for (int q = 0; q < 2; ++q) {
                int idx = q * NTHR + tid;
                if (idx < 520) {
                    int r = base + idx;
                    const float4* w4 = (const float4*)(W1 + (size_t)r * DIN);
                    const float4* k4 = (const float4*)s_knet;
                    float acc = b1[r];
#pragma unroll
                    for (int c = 0; c < DIN / 4; ++c) {
                        float4 a = w4[c], b = k4[c];
                        acc = fmaf(a.x, b.x, acc); acc = fmaf(a.y, b.y, acc);
                        acc = fmaf(a.z, b.z, acc); acc = fmaf(a.w, b.w, acc);
                    }
                    g_l1h[r] = __float2half(fmaxf(acc, 0.f));
                }
            }
            signal_done(&g_l1done);
        }

        // ---------- Whh blocks: gh rows ----------
        if (bid >= WHH_LO) {
            int gw = (bid - WHH_LO) * NWARP + wid;    // 0..1583
#pragma unroll
            for (int q = 0; q < 2; ++q) {
                int u = gw + q * WHH_WARPS;
                if (u < HID_) {
                    float3 g = dot3_hh(w_hhH + (size_t)u * HID_,
                                       w_hhH + (size_t)(u + HID_) * HID_,
                                       w_hhH + (size_t)(u + 2 * HID_) * HID_,
                                       s_x, HID_ / 8);
                    if (lane == 0) {
                        g_gh[u]            = g.x + bhh[u];
                        g_gh[u + HID_]     = g.y + bhh[u + HID_];
                        g_gh[u + 2 * HID_] = g.z + bhh[u + 2 * HID_];
                    }
                }
            }
            signal_done(&g_ghdone);
        }

        // ---------- all blocks: gi (3 interleaved rows) + gate ----------
        wait_ctr(&g_l1done, 8u * (unsigned)(t + 1));
        {
            const uint4* src = (const uint4*)g_l1h;
            for (int i = tid; i < H1_ / 8; i += NTHR) s_x[i] = src[i];
        }
        __syncthreads();
        {
            int u = bid + NBLK * wid;
            if (u < HID_) {
                float3 g = dot3_hh(w_ihH + (size_t)u * H1_,
                                   w_ihH + (size_t)(u + HID_) * H1_,
                                   w_ihH + (size_t)(u + 2 * HID_) * H1_,
                                   s_x, H1_ / 8);
                if (lane == 0) {
                    s_gi3[wid][0] = g.x + bih[u];
                    s_gi3[wid][1] = g.y + bih[u + HID_];
                    s_gi3[wid][2] = g.z + bih[u + 2 * HID_];
                }
            }
        }
        wait_ctr(&g_ghdone, (unsigned)WHH_NB * (unsigned)(t + 1));
        if (tid < NWARP) {
            int u = bid + NBLK * tid;
            if (u < HID_) {
                float hold = (t == 0) ? h0[u] : g_hf[u];
                float rg = sigmoidf_(s_gi3[tid][0] + g_gh[u]);
                float zg = sigmoidf_(s_gi3[tid][1] + g_gh[u + HID_]);
                float ng = tanhf(s_gi3[tid][2] + rg * g_gh[u + 2 * HID_]);
                float hv = (1.f - zg) * ng + zg * hold;
                g_hf[u]  = hv;
                g_hh2[u] = __float2half(hv);
            }
        }
        grid_barrier();
    }

    // ================= epilogue: x_post(T-1) =================
    if (bid >= W2_LO && bid <= W2_HI) {
        const uint4* src = (const uint4*)g_hh2;
        for (int i = tid; i < HID_ / 8; i += NTHR) s_x[i] = src[i];
        __syncthreads();
        int r = (bid - W2_LO) + 48 * wid;
        float v = warp_dot_hh(w2H + (size_t)r * HID_, s_x, HID_ / 8);
        if (lane == 0) g_l2[r] = fmaxf(v + b2[r], 0.f);
        signal_done(&g_l2done);
    }
    if (bid >= W3_LO && bid <= W3_HI) {
        wait_ctr(&g_l2done, 48u * (unsigned)T_LEN);
        for (int i = tid; i < H2_; i += NTHR) s_l2f[i] = g_l2[i];
        __syncthreads();
        if (wid < 12) {
            int r = (bid - W3_LO) + 16 * wid;
            float v = warp_dot_f(W3 + (size_t)r * H2_, s_l2f);
            if (lane == 0) g_z[r] = (v + b3[r]) * 1e-4f;
        }
        signal_done(&g_zdone);
    }
    if (bid == 0) {
        wait_ctr(&g_zdone, 16u * (unsigned)T_LEN);
        if (tid < DOUT) s_z[tid] = g_z[tid];
        __syncthreads();
        if (tid < M_) {
            float acc = 0.f;
#pragma unroll 4
            for (int j = 0; j < N_; ++j) acc = fmaf(s_z[tid * N_ + j], s_dy[j], acc);
            out[tid * T_LEN + (T_LEN - 1)] = s_xprior[tid] + acc;
        }
        __syncthreads();
        if (tid == 0) {
            // reset all sync state for graph replay
            __threadfence();
            *((volatile unsigned*)&g_l2done)   = 0u;
            *((volatile unsigned*)&g_zdone)    = 0u;
            *((volatile unsigned*)&g_knetflag) = 0u;
            *((volatile unsigned*)&g_l1done)   = 0u;
            *((volatile unsigned*)&g_ghdone)   = 0u;
            *((volatile unsigned*)&g_bar_count) = 0u;
            *((volatile unsigned*)&g_bar_gen)   = 0u;
            __threadfence();
        }
    }
}

// ---------------- launch ----------------
extern "C" void kernel_launch(void* const* d_in, const int* in_sizes, int n_in,
                              void* d_out, int out_size) {
    const float* A    = (const float*)d_in[0];
    const float* C    = (const float*)d_in[1];
    const float* x0   = (const float*)d_in[2];
    const float* h0   = (const float*)d_in[3];
    const float* y    = (const float*)d_in[4];
    const float* W1   = (const float*)d_in[5];
    const float* b1   = (const float*)d_in[6];
    const float* Wih  = (const float*)d_in[7];
    const float* Whh  = (const float*)d_in[8];
    const float* bih  = (const float*)d_in[9];
    const float* bhh  = (const float*)d_in[10];
    const float* W2   = (const float*)d_in[11];
    const float* b2   = (const float*)d_in[12];
    const float* W3   = (const float*)d_in[13];
    const float* b3   = (const float*)d_in[14];
    float* out = (float*)d_out;

    cvt_kernel<<<2048, 256>>>(Wih, Whh, W2);
    kalmannet_kernel<<<NBLK, NTHR>>>(A, C, x0, h0, y, W1, b1, bih, bhh,
                                     b2, W3, b3, out);
}

// round 6
// speedup vs baseline: 1.5628x; 1.3796x over previous
#include <cuda_runtime.h>
#include <cuda_fp16.h>
#include <math.h>

// Problem dims
#define T_LEN 512
#define M_    4
#define N_    48
#define DIN   52
#define H1_   4160
#define HID_  2320
#define G3_   6960
#define H2_   768
#define DOUT  192

#define NBLK  148
#define NTHR  512
#define NWARP 16

// roles
#define W2_LO   1
#define W2_HI   48     // 48 blocks, 16 rows each
#define W3_LO   1
#define W3_HI   16     // 16 blocks, 12 rows each
#define W1_LO   17
#define W1_HI   24     // 8 blocks, 520 rows each
#define WHH_LO  49     // 99 blocks
#define WHH_NB  99
#define WHH_WARPS (WHH_NB * NWARP)   // 1584

// ---------------- device scratch ----------------
__device__ __align__(16) __half w_ihH[(size_t)G3_ * H1_];   // row-major, 57.9MB
__device__ __align__(16) __half w_hhH[(size_t)G3_ * HID_];  // 32.3MB
__device__ __align__(16) __half w2H[(size_t)H2_ * HID_];    // 3.6MB

__device__ __align__(16) float  g_hf[HID_];      // fp32 hidden (hold)
__device__ __align__(16) __half g_hh2[HID_];     // fp16 hidden (matvec)
__device__ __align__(16) __half g_l1h[H1_];      // l1 fp16
__device__ __align__(16) float  g_gh[G3_];
__device__ __align__(16) float  g_l2[H2_];
__device__ __align__(16) float  g_z[DOUT];
__device__ __align__(16) float  g_knet[DIN + 4];
__device__ unsigned g_l2done, g_zdone, g_knetflag, g_l1done, g_ghdone;
__device__ unsigned g_bar_count, g_bar_gen;

// ---------------- conversion kernel ----------------
__device__ __forceinline__ void cvt8(const float* __restrict__ src,
                                     __half* __restrict__ dst, size_t g) {
    const float4* s4 = (const float4*)src;
    float4 a = s4[2 * g], b = s4[2 * g + 1];
    __half2 h0 = __floats2half2_rn(a.x, a.y);
    __half2 h1 = __floats2half2_rn(a.z, a.w);
    __half2 h2 = __floats2half2_rn(b.x, b.y);
    __half2 h3 = __floats2half2_rn(b.z, b.w);
    uint4 o;
    o.x = *(unsigned*)&h0; o.y = *(unsigned*)&h1;
    o.z = *(unsigned*)&h2; o.w = *(unsigned*)&h3;
    ((uint4*)dst)[g] = o;
}

__global__ void cvt_kernel(const float* __restrict__ Wih,
                           const float* __restrict__ Whh,
                           const float* __restrict__ W2) {
    size_t i0 = (size_t)blockIdx.x * blockDim.x + threadIdx.x;
    size_t st = (size_t)gridDim.x * blockDim.x;
    const size_t nIH = (size_t)G3_ * H1_ / 8, nHH = (size_t)G3_ * HID_ / 8;
    const size_t n2 = (size_t)H2_ * HID_ / 8;
    for (size_t g = i0; g < nIH; g += st) cvt8(Wih, w_ihH, g);
    for (size_t g = i0; g < nHH; g += st) cvt8(Whh, w_hhH, g);
    for (size_t g = i0; g < n2;  g += st) cvt8(W2, w2H, g);
}

// ---------------- lightweight grid barrier (tid0-only fence) ---------------
__device__ __forceinline__ void grid_barrier() {
    __syncthreads();
    if (threadIdx.x == 0) {
        __threadfence();
        unsigned gen = *((volatile unsigned*)&g_bar_gen);
        if (atomicAdd(&g_bar_count, 1u) == (unsigned)gridDim.x - 1u) {
            *((volatile unsigned*)&g_bar_count) = 0u;
            __threadfence();
            *((volatile unsigned*)&g_bar_gen) = gen + 1u;
        } else {
            while (*((volatile unsigned*)&g_bar_gen) == gen) { }
        }
        __threadfence();
    }
    __syncthreads();
}

__device__ __forceinline__ void signal_done(unsigned* ctr) {
    __syncthreads();
    if (threadIdx.x == 0) { __threadfence(); atomicAdd(ctr, 1u); }
}
__device__ __forceinline__ void wait_ctr(unsigned* ctr, unsigned target) {
    if (threadIdx.x == 0) {
        while (*((volatile unsigned*)ctr) < target) { }
        __threadfence();
    }
    __syncthreads();
}

#define H2AT(u) (*(const __half2*)&(u))

// ---------------- batched dots (explicit MLP) ----------------
// single fp16 row x half2 smem vector; batch-8 load blocks
__device__ __forceinline__ float warp_dot_hh(const __half* __restrict__ w,
                                             const uint4* __restrict__ xs,
                                             int n8) {
    const uint4* w4 = (const uint4*)w;
    int lane = threadIdx.x & 31;
    __half2 z = __float2half2_rn(0.f);
    __half2 a0 = z, a1 = z, a2 = z, a3 = z;
    const int kfull = n8 >> 5;
    int k = 0;
    for (; k + 8 <= kfull; k += 8) {
        uint4 wv[8], xv[8];
#pragma unroll
        for (int j = 0; j < 8; ++j) wv[j] = w4[(k + j) * 32 + lane];
#pragma unroll
        for (int j = 0; j < 8; ++j) xv[j] = xs[(k + j) * 32 + lane];
#pragma unroll
        for (int j = 0; j < 8; ++j) {
            a0 = __hfma2(H2AT(wv[j].x), H2AT(xv[j].x), a0);
            a1 = __hfma2(H2AT(wv[j].y), H2AT(xv[j].y), a1);
            a2 = __hfma2(H2AT(wv[j].z), H2AT(xv[j].z), a2);
            a3 = __hfma2(H2AT(wv[j].w), H2AT(xv[j].w), a3);
        }
    }
    for (; k < kfull; ++k) {
        uint4 wv = w4[k * 32 + lane], xv = xs[k * 32 + lane];
        a0 = __hfma2(H2AT(wv.x), H2AT(xv.x), a0);
        a1 = __hfma2(H2AT(wv.y), H2AT(xv.y), a1);
        a2 = __hfma2(H2AT(wv.z), H2AT(xv.z), a2);
        a3 = __hfma2(H2AT(wv.w), H2AT(xv.w), a3);
    }
    {
        int c = kfull * 32 + lane;
        if (c < n8) {
            uint4 wv = w4[c], xv = xs[c];
            a0 = __hfma2(H2AT(wv.x), H2AT(xv.x), a0);
            a1 = __hfma2(H2AT(wv.y), H2AT(xv.y), a1);
            a2 = __hfma2(H2AT(wv.z), H2AT(xv.z), a2);
            a3 = __hfma2(H2AT(wv.w), H2AT(xv.w), a3);
        }
    }
    float2 f0 = __half22float2(a0), f1 = __half22float2(a1);
    float2 f2 = __half22float2(a2), f3 = __half22float2(a3);
    float acc = ((f0.x + f0.y) + (f1.x + f1.y)) + ((f2.x + f2.y) + (f3.x + f3.y));
#pragma unroll
    for (int o = 16; o; o >>= 1) acc += __shfl_down_sync(0xffffffffu, acc, o);
    return acc;
}

// 3 interleaved fp16 rows x half2 smem vector; batch-4 (12 global loads/block)
__device__ __forceinline__ float3 dot3_hh(const __half* __restrict__ wa,
                                          const __half* __restrict__ wb,
                                          const __half* __restrict__ wc,
                                          const uint4* __restrict__ xs,
                                          int n8) {
    const uint4* A  = (const uint4*)wa;
    const uint4* B  = (const uint4*)wb;
    const uint4* Cc = (const uint4*)wc;
    int lane = threadIdx.x & 31;
    __half2 z = __float2half2_rn(0.f);
    __half2 a0 = z, a1 = z, a2 = z, a3 = z;
    __half2 b0 = z, b1 = z, b2 = z, b3 = z;
    __half2 c0 = z, c1 = z, c2 = z, c3 = z;
    const int kfull = n8 >> 5;
    int k = 0;
    for (; k + 4 <= kfull; k += 4) {
        uint4 wA[4], wB[4], wC[4], xv[4];
#pragma unroll
        for (int j = 0; j < 4; ++j) wA[j] = A[(k + j) * 32 + lane];
#pragma unroll
        for (int j = 0; j < 4; ++j) wB[j] = B[(k + j) * 32 + lane];
#pragma unroll
        for (int j = 0; j < 4; ++j) wC[j] = Cc[(k + j) * 32 + lane];
#pragma unroll
        for (int j = 0; j < 4; ++j) xv[j] = xs[(k + j) * 32 + lane];
#pragma unroll
        for (int j = 0; j < 4; ++j) {
            a0 = __hfma2(H2AT(wA[j].x), H2AT(xv[j].x), a0);
            a1 = __hfma2(H2AT(wA[j].y), H2AT(xv[j].y), a1);
            a2 = __hfma2(H2AT(wA[j].z), H2AT(xv[j].z), a2);
            a3 = __hfma2(H2AT(wA[j].w), H2AT(xv[j].w), a3);
            b0 = __hfma2(H2AT(wB[j].x), H2AT(xv[j].x), b0);
            b1 = __hfma2(H2AT(wB[j].y), H2AT(xv[j].y), b1);
            b2 = __hfma2(H2AT(wB[j].z), H2AT(xv[j].z), b2);
            b3 = __hfma2(H2AT(wB[j].w), H2AT(xv[j].w), b3);
            c0 = __hfma2(H2AT(wC[j].x), H2AT(xv[j].x), c0);
            c1 = __hfma2(H2AT(wC[j].y), H2AT(xv[j].y), c1);
            c2 = __hfma2(H2AT(wC[j].z), H2AT(xv[j].z), c2);
            c3 = __hfma2(H2AT(wC[j].w), H2AT(xv[j].w), c3);
        }
    }
    for (; k < kfull; ++k) {
        int c = k * 32 + lane;
        uint4 u = A[c], v = B[c], w = Cc[c], xv = xs[c];
        a0 = __hfma2(H2AT(u.x), H2AT(xv.x), a0);
        a1 = __hfma2(H2AT(u.y), H2AT(xv.y), a1);
        a2 = __hfma2(H2AT(u.z), H2AT(xv.z), a2);
        a3 = __hfma2(H2AT(u.w), H2AT(xv.w), a3);
        b0 = __hfma2(H2AT(v.x), H2AT(xv.x), b0);
        b1 = __hfma2(H2AT(v.y), H2AT(xv.y), b1);
        b2 = __hfma2(H2AT(v.z), H2AT(xv.z), b2);
        b3 = __hfma2(H2AT(v.w), H2AT(xv.w), b3);
        c0 = __hfma2(H2AT(w.x), H2AT(xv.x), c0);
        c1 = __hfma2(H2AT(w.y), H2AT(xv.y), c1);
        c2 = __hfma2(H2AT(w.z), H2AT(xv.z), c2);
        c3 = __hfma2(H2AT(w.w), H2AT(xv.w), c3);
    }
    {
        int c = kfull * 32 + lane;
        if (c < n8) {
            uint4 u = A[c], v = B[c], w = Cc[c], xv = xs[c];
            a0 = __hfma2(H2AT(u.x), H2AT(xv.x), a0);
            a1 = __hfma2(H2AT(u.y), H2AT(xv.y), a1);
            a2 = __hfma2(H2AT(u.z), H2AT(xv.z), a2);
            a3 = __hfma2(H2AT(u.w), H2AT(xv.w), a3);
            b0 = __hfma2(H2AT(v.x), H2AT(xv.x), b0);
            b1 = __hfma2(H2AT(v.y), H2AT(xv.y), b1);
            b2 = __hfma2(H2AT(v.z), H2AT(xv.z), b2);
            b3 = __hfma2(H2AT(v.w), H2AT(xv.w), b3);
            c0 = __hfma2(H2AT(w.x), H2AT(xv.x), c0);
            c1 = __hfma2(H2AT(w.y), H2AT(xv.y), c1);
            c2 = __hfma2(H2AT(w.z), H2AT(xv.z), c2);
            c3 = __hfma2(H2AT(w.w), H2AT(xv.w), c3);
        }
    }
    float2 fa0 = __half22float2(a0), fa1 = __half22float2(a1);
    float2 fa2 = __half22float2(a2), fa3 = __half22float2(a3);
    float2 fb0 = __half22float2(b0), fb1 = __half22float2(b1);
    float2 fb2 = __half22float2(b2), fb3 = __half22float2(b3);
    float2 fc0 = __half22float2(c0), fc1 = __half22float2(c1);
    float2 fc2 = __half22float2(c2), fc3 = __half22float2(c3);
    float ra = ((fa0.x + fa0.y) + (fa1.x + fa1.y)) + ((fa2.x + fa2.y) + (fa3.x + fa3.y));
    float rb = ((fb0.x + fb0.y) + (fb1.x + fb1.y)) + ((fb2.x + fb2.y) + (fb3.x + fb3.y));
    float rc = ((fc0.x + fc0.y) + (fc1.x + fc1.y)) + ((fc2.x + fc2.y) + (fc3.x + fc3.y));
#pragma unroll
    for (int o = 16; o; o >>= 1) {
        ra += __shfl_down_sync(0xffffffffu, ra, o);
        rb += __shfl_down_sync(0xffffffffu, rb, o);
        rc += __shfl_down_sync(0xffffffffu, rc, o);
    }
    return make_float3(ra, rb, rc);
}

// fp32 row dot over H2 (W3)
__device__ __forceinline__ float warp_dot_f(const float* __restrict__ w,
                                            const float* __restrict__ x) {
    const float4* w4 = (const float4*)w;
    const float4* x4 = (const float4*)x;
    int lane = threadIdx.x & 31;
    float a0 = 0.f, a1 = 0.f, a2 = 0.f, a3 = 0.f;
#pragma unroll
    for (int c = lane; c < H2_ / 4; c += 32) {
        float4 a = w4[c], b = x4[c];
        a0 = fmaf(a.x, b.x, a0); a1 = fmaf(a.y, b.y, a1);
        a2 = fmaf(a.z, b.z, a2); a3 = fmaf(a.w, b.w, a3);
    }
    float acc = (a0 + a1) + (a2 + a3);
#pragma unroll
    for (int o = 16; o; o >>= 1) acc += __shfl_down_sync(0xffffffffu, acc, o);
    return acc;
}

__device__ __forceinline__ float sigmoidf_(float x) {
    return 1.f / (1.f + __expf(-x));
}

// ---------------- persistent kernel ----------------
__global__ void __launch_bounds__(NTHR, 1)
kalmannet_kernel(const float* __restrict__ A,   const float* __restrict__ C,
                 const float* __restrict__ x0,  const float* __restrict__ h0,
                 const float* __restrict__ y,   const float* __restrict__ W1,
                 const float* __restrict__ b1,  const float* __restrict__ bih,
                 const float* __restrict__ bhh, const float* __restrict__ b2,
                 const float* __restrict__ W3,  const float* __restrict__ b3,
                 float* __restrict__ out) {
    const int tid  = threadIdx.x;
    const int bid  = blockIdx.x;
    const int wid  = tid >> 5;
    const int lane = tid & 31;

    __shared__ __align__(16) uint4 s_x[H1_ / 8];
    __shared__ __align__(16) float s_l2f[H2_];
    __shared__ __align__(16) float s_z[DOUT];
    __shared__ __align__(16) float s_knet[56];
    __shared__ __align__(16) float s_gi3[NWARP][4];
    __shared__ float s_dy[N_];
    __shared__ float s_xprior[M_], s_xpost[M_], s_xprev[M_];

    for (int t = 0; t < T_LEN; ++t) {
        // ---------- stage h(t-1) as half2 ----------
        if ((bid >= W2_LO && bid <= W2_HI && t > 0) || bid >= WHH_LO) {
            if (t == 0) {
                for (int i = tid; i < HID_ / 2; i += NTHR) {
                    float2 f = ((const float2*)h0)[i];
                    ((__half2*)s_x)[i] = __floats2half2_rn(f.x, f.y);
                }
            } else {
                const uint4* src = (const uint4*)g_hh2;
                for (int i = tid; i < HID_ / 8; i += NTHR) s_x[i] = src[i];
            }
            __syncthreads();
        }

        // ---------- W2: l2(t-1) ----------
        if (bid >= W2_LO && bid <= W2_HI && t > 0) {
            int r = (bid - W2_LO) + 48 * wid;
            float v = warp_dot_hh(w2H + (size_t)r * HID_, s_x, HID_ / 8);
            if (lane == 0) g_l2[r] = fmaxf(v + b2[r], 0.f);
            signal_done(&g_l2done);
        }

        // ---------- W3: z(t-1) ----------
        if (bid >= W3_LO && bid <= W3_HI && t > 0) {
            wait_ctr(&g_l2done, 48u * (unsigned)t);
            for (int i = tid; i < H2_; i += NTHR) s_l2f[i] = g_l2[i];
            __syncthreads();
            if (wid < 12) {
                int r = (bid - W3_LO) + 16 * wid;
                float v = warp_dot_f(W3 + (size_t)r * H2_, s_l2f);
                if (lane == 0) g_z[r] = (v + b3[r]) * 1e-4f;
            }
            signal_done(&g_zdone);
        }

        // ---------- block 0: serial chain -> knet ----------
        if (bid == 0) {
            if (t == 0) {
                if (tid < M_) { s_xpost[tid] = x0[tid]; s_xprev[tid] = x0[tid]; }
                __syncthreads();
            } else {
                wait_ctr(&g_zdone, 16u * (unsigned)t);
                if (tid < DOUT) s_z[tid] = g_z[tid];
                __syncthreads();
                if (tid < M_) {
                    float acc = 0.f;
#pragma unroll 4
                    for (int j = 0; j < N_; ++j)
                        acc = fmaf(s_z[tid * N_ + j], s_dy[j], acc);
                    float xp = s_xprior[tid] + acc;
                    s_xprev[tid] = s_xprior[tid];
                    s_xpost[tid] = xp;
                    out[tid * T_LEN + (t - 1)] = xp;
                }
                __syncthreads();
            }
            if (tid < M_) {
                float acc = 0.f;
#pragma unroll
                for (int k = 0; k < M_; ++k) acc = fmaf(A[tid * M_ + k], s_xpost[k], acc);
                s_xprior[tid] = acc;
            }
            __syncthreads();
            if (wid == 0) {
                for (int j = lane; j < N_; j += 32) {
                    float m = C[j * (M_ + 1) + M_];
#pragma unroll
                    for (int k = 0; k < M_; ++k) m = fmaf(C[j * (M_ + 1) + k], s_xprior[k], m);
                    s_dy[j] = y[j * T_LEN + t] - m;
                }
                __syncwarp();
                float sq = 0.f;
                for (int j = lane; j < N_; j += 32) sq += s_dy[j] * s_dy[j];
#pragma unroll
                for (int o = 16; o; o >>= 1) sq += __shfl_down_sync(0xffffffffu, sq, o);
                sq = __shfl_sync(0xffffffffu, sq, 0);
                float inv = 1.f / fmaxf(sqrtf(sq), 1e-12f);
                for (int j = lane; j < N_; j += 32) g_knet[j] = s_dy[j] * inv;

                float dx = (lane < M_) ? (s_xpost[lane] - s_xprev[lane]) : 0.f;
                float sq2 = dx * dx;
#pragma unroll
                for (int o = 16; o; o >>= 1) sq2 += __shfl_down_sync(0xffffffffu, sq2, o);
                sq2 = __shfl_sync(0xffffffffu, sq2, 0);
                float inv2 = 1.f / fmaxf(sqrtf(sq2), 1e-12f);
                if (lane < M_) g_knet[N_ + lane] = dx * inv2;
                __syncwarp();
                if (lane == 0) {
                    __threadfence();
                    *((volatile unsigned*)&g_knetflag) = (unsigned)(t + 1);
                }
            }
        }

        // ---------- W1 blocks: l1 ----------
        if (bid >= W1_LO && bid <= W1_HI) {
            if (tid == 0) {
                while (*((volatile unsigned*)&g_knetflag) < (unsigned)(t + 1)) { }
                __threadfence();
            }
            __syncthreads();
            if (tid < DIN) s_knet[tid] = g_knet[tid];
            __syncthreads();
            int base = (bid - W1_LO) * 520;
#pragma unroll
            for (int q = 0; q < 2; ++q) {
                int idx = q * NTHR + tid;
                if (idx < 520) {
                    int r = base + idx;
                    const float4* w4 = (const float4*)(W1 + (size_t)r * DIN);
                    const float4* k4 = (const float4*)s_knet;
                    float acc = b1[r];
#pragma unroll
                    for (int c = 0; c < DIN / 4; ++c) {
                        float4 a = w4[c], b = k4[c];
                        acc = fmaf(a.x, b.x, acc); acc = fmaf(a.y, b.y, acc);
                        acc = fmaf(a.z, b.z, acc); acc = fmaf(a.w, b.w, acc);
                    }
                    g_l1h[r] = __float2half(fmaxf(acc, 0.f));
                }
            }
            signal_done(&g_l1done);
        }

        // ---------- Whh blocks: gh rows ----------
        if (bid >= WHH_LO) {
            int gw = (bid - WHH_LO) * NWARP + wid;
#pragma unroll
            for (int q = 0; q < 2; ++q) {
                int u = gw + q * WHH_WARPS;
                if (u < HID_) {
                    float3 g = dot3_hh(w_hhH + (size_t)u * HID_,
                                       w_hhH + (size_t)(u + HID_) * HID_,
                                       w_hhH + (size_t)(u + 2 * HID_) * HID_,
                                       s_x, HID_ / 8);
                    if (lane == 0) {
                        g_gh[u]            = g.x + bhh[u];
                        g_gh[u + HID_]     = g.y + bhh[u + HID_];
                        g_gh[u + 2 * HID_] = g.z + bhh[u + 2 * HID_];
                    }
                }
            }
            signal_done(&g_ghdone);
        }

        // ---------- all blocks: gi + gate ----------
        wait_ctr(&g_l1done, 8u * (unsigned)(t + 1));
        {
            const uint4* src = (const uint4*)g_l1h;
            for (int i = tid; i < H1_ / 8; i += NTHR) s_x[i] = src[i];
        }
        __syncthreads();
        {
            int u = bid + NBLK * wid;
            if (u < HID_) {
                float3 g = dot3_hh(w_ihH + (size_t)u * H1_,
                                   w_ihH + (size_t)(u + HID_) * H1_,
                                   w_ihH + (size_t)(u + 2 * HID_) * H1_,
                                   s_x, H1_ / 8);
                if (lane == 0) {
                    s_gi3[wid][0] = g.x + bih[u];
                    s_gi3[wid][1] = g.y + bih[u + HID_];
                    s_gi3[wid][2] = g.z + bih[u + 2 * HID_];
                }
            }
        }
        wait_ctr(&g_ghdone, (unsigned)WHH_NB * (unsigned)(t + 1));
        if (tid < NWARP) {
            int u = bid + NBLK * tid;
            if (u < HID_) {
                float hold = (t == 0) ? h0[u] : g_hf[u];
                float rg = sigmoidf_(s_gi3[tid][0] + g_gh[u]);
                float zg = sigmoidf_(s_gi3[tid][1] + g_gh[u + HID_]);
                float ng = tanhf(s_gi3[tid][2] + rg * g_gh[u + 2 * HID_]);
                float hv = (1.f - zg) * ng + zg * hold;
                g_hf[u]  = hv;
                g_hh2[u] = __float2half(hv);
            }
        }
        grid_barrier();
    }

    // ================= epilogue: x_post(T-1) =================
    if (bid >= W2_LO && bid <= W2_HI) {
        const uint4* src = (const uint4*)g_hh2;
        for (int i = tid; i < HID_ / 8; i += NTHR) s_x[i] = src[i];
        __syncthreads();
        int r = (bid - W2_LO) + 48 * wid;
        float v = warp_dot_hh(w2H + (size_t)r * HID_, s_x, HID_ / 8);
        if (lane == 0) g_l2[r] = fmaxf(v + b2[r], 0.f);
        signal_done(&g_l2done);
    }
    if (bid >= W3_LO && bid <= W3_HI) {
        wait_ctr(&g_l2done, 48u * (unsigned)T_LEN);
        for (int i = tid; i < H2_; i += NTHR) s_l2f[i] = g_l2[i];
        __syncthreads();
        if (wid < 12) {
            int r = (bid - W3_LO) + 16 * wid;
            float v = warp_dot_f(W3 + (size_t)r * H2_, s_l2f);
            if (lane == 0) g_z[r] = (v + b3[r]) * 1e-4f;
        }
        signal_done(&g_zdone);
    }
    if (bid == 0) {
        wait_ctr(&g_zdone, 16u * (unsigned)T_LEN);
        if (tid < DOUT) s_z[tid] = g_z[tid];
        __syncthreads();
        if (tid < M_) {
            float acc = 0.f;
#pragma unroll 4
            for (int j = 0; j < N_; ++j) acc = fmaf(s_z[tid * N_ + j], s_dy[j], acc);
            out[tid * T_LEN + (T_LEN - 1)] = s_xprior[tid] + acc;
        }
        __syncthreads();
        if (tid == 0) {
            __threadfence();
            *((volatile unsigned*)&g_l2done)   = 0u;
            *((volatile unsigned*)&g_zdone)    = 0u;
            *((volatile unsigned*)&g_knetflag) = 0u;
            *((volatile unsigned*)&g_l1done)   = 0u;
            *((volatile unsigned*)&g_ghdone)   = 0u;
            *((volatile unsigned*)&g_bar_count) = 0u;
            *((volatile unsigned*)&g_bar_gen)   = 0u;
            __threadfence();
        }
    }
}

// ---------------- launch ----------------
extern "C" void kernel_launch(void* const* d_in, const int* in_sizes, int n_in,
                              void* d_out, int out_size) {
    const float* A    = (const float*)d_in[0];
    const float* C    = (const float*)d_in[1];
    const float* x0   = (const float*)d_in[2];
    const float* h0   = (const float*)d_in[3];
    const float* y    = (const float*)d_in[4];
    const float* W1   = (const float*)d_in[5];
    const float* b1   = (const float*)d_in[6];
    const float* Wih  = (const float*)d_in[7];
    const float* Whh  = (const float*)d_in[8];
    const float* bih  = (const float*)d_in[9];
    const float* bhh  = (const float*)d_in[10];
    const float* W2   = (const float*)d_in[11];
    const float* b2   = (const float*)d_in[12];
    const float* W3   = (const float*)d_in[13];
    const float* b3   = (const float*)d_in[14];
    float* out = (float*)d_out;

    cvt_kernel<<<2048, 256>>>(Wih, Whh, W2);
    kalmannet_kernel<<<NBLK, NTHR>>>(A, C, x0, h0, y, W1, b1, bih, bhh,
                                     b2, W3, b3, out);
}

// round 8
// speedup vs baseline: 1.7885x; 1.1444x over previous
#include <cuda_runtime.h>
#include <cuda_fp16.h>
#include <math.h>

// Problem dims
#define T_LEN 512
#define M_    4
#define N_    48
#define DIN   52
#define H1_   4160
#define HID_  2320
#define G3_   6960
#define H2_   768
#define DOUT  192

#define NBLK  148
#define NTHR  512
#define NWARP 16

// roles
#define W2_LO   1
#define W2_HI   48
#define W3_LO   1
#define W3_HI   16
#define W1_LO   17
#define W1_HI   24
#define WHH_LO  49
#define WHH_NB  99
#define WHH_WARPS (WHH_NB * NWARP)   // 1584

// ---------------- device scratch ----------------
__device__ __align__(16) __half w_ihH[(size_t)G3_ * H1_];
__device__ __align__(16) __half w_hhH[(size_t)G3_ * HID_];
__device__ __align__(16) __half w2H[(size_t)H2_ * HID_];

__device__ __align__(16) float  g_hf[HID_];
__device__ __align__(16) __half g_hh2[HID_];
__device__ __align__(16) __half g_l1h[H1_];
__device__ __align__(16) float  g_gh[G3_];
__device__ __align__(16) float  g_l2[H2_];
__device__ __align__(16) float  g_z[DOUT];
__device__ __align__(16) float  g_knet[DIN + 4];
__device__ unsigned g_l2done, g_zdone, g_knetflag, g_l1done, g_ghdone;
__device__ unsigned g_bar_count, g_bar_gen;

// ---------------- conversion kernel ----------------
__device__ __forceinline__ void cvt8(const float* __restrict__ src,
                                     __half* __restrict__ dst, size_t g) {
    const float4* s4 = (const float4*)src;
    float4 a = s4[2 * g], b = s4[2 * g + 1];
    __half2 h0 = __floats2half2_rn(a.x, a.y);
    __half2 h1 = __floats2half2_rn(a.z, a.w);
    __half2 h2 = __floats2half2_rn(b.x, b.y);
    __half2 h3 = __floats2half2_rn(b.z, b.w);
    uint4 o;
    o.x = *(unsigned*)&h0; o.y = *(unsigned*)&h1;
    o.z = *(unsigned*)&h2; o.w = *(unsigned*)&h3;
    ((uint4*)dst)[g] = o;
}

__global__ void cvt_kernel(const float* __restrict__ Wih,
                           const float* __restrict__ Whh,
                           const float* __restrict__ W2) {
    size_t i0 = (size_t)blockIdx.x * blockDim.x + threadIdx.x;
    size_t st = (size_t)gridDim.x * blockDim.x;
    const size_t nIH = (size_t)G3_ * H1_ / 8, nHH = (size_t)G3_ * HID_ / 8;
    const size_t n2 = (size_t)H2_ * HID_ / 8;
    for (size_t g = i0; g < nIH; g += st) cvt8(Wih, w_ihH, g);
    for (size_t g = i0; g < nHH; g += st) cvt8(Whh, w_hhH, g);
    for (size_t g = i0; g < n2;  g += st) cvt8(W2, w2H, g);
}

// ---------------- sync primitives ----------------
__device__ __forceinline__ void grid_barrier() {
    __syncthreads();
    if (threadIdx.x == 0) {
        __threadfence();
        unsigned gen = *((volatile unsigned*)&g_bar_gen);
        if (atomicAdd(&g_bar_count, 1u) == (unsigned)gridDim.x - 1u) {
            *((volatile unsigned*)&g_bar_count) = 0u;
            __threadfence();
            *((volatile unsigned*)&g_bar_gen) = gen + 1u;
        } else {
            while (*((volatile unsigned*)&g_bar_gen) == gen) { }
        }
        __threadfence();
    }
    __syncthreads();
}

__device__ __forceinline__ void signal_done(unsigned* ctr) {
    __syncthreads();
    if (threadIdx.x == 0) { __threadfence(); atomicAdd(ctr, 1u); }
}
__device__ __forceinline__ void wait_ctr(unsigned* ctr, unsigned target) {
    if (threadIdx.x == 0) {
        while (*((volatile unsigned*)ctr) < target) { }
        __threadfence();
    }
    __syncthreads();
}

#define H2AT(u) (*(const __half2*)&(u))

// ---------------- software-pipelined dots ----------------
// 3 interleaved rows, depth-3 register ring, fully unrolled.
template <int N8>
__device__ __forceinline__ float3 dot3_pipe(const __half* __restrict__ wa,
                                            const __half* __restrict__ wb,
                                            const __half* __restrict__ wc,
                                            const uint4* __restrict__ xs) {
    constexpr int KF  = N8 / 32;
    constexpr int REM = N8 - KF * 32;
    constexpr int D   = 3;
    const uint4* A  = (const uint4*)wa;
    const uint4* B  = (const uint4*)wb;
    const uint4* Cc = (const uint4*)wc;
    const int lane = threadIdx.x & 31;
    uint4 bufA[D], bufB[D], bufC[D], bufX[D];
#pragma unroll
    for (int s = 0; s < D; ++s) {
        if (s < KF) {
            int c = s * 32 + lane;
            bufA[s] = A[c]; bufB[s] = B[c]; bufC[s] = Cc[c]; bufX[s] = xs[c];
        }
    }
    __half2 z = __float2half2_rn(0.f);
    __half2 a0 = z, a1 = z, a2 = z, a3 = z;
    __half2 b0 = z, b1 = z, b2 = z, b3 = z;
    __half2 c0 = z, c1 = z, c2 = z, c3 = z;
#pragma unroll
    for (int k = 0; k < KF; ++k) {
        const int sl = k % D;
        uint4 u = bufA[sl], v = bufB[sl], w = bufC[sl], xv = bufX[sl];
        const int kn = k + D;
        if (kn < KF) {
            int c = kn * 32 + lane;
            bufA[sl] = A[c]; bufB[sl] = B[c]; bufC[sl] = Cc[c]; bufX[sl] = xs[c];
        }
        a0 = __hfma2(H2AT(u.x), H2AT(xv.x), a0);
        a1 = __hfma2(H2AT(u.y), H2AT(xv.y), a1);
        a2 = __hfma2(H2AT(u.z), H2AT(xv.z), a2);
        a3 = __hfma2(H2AT(u.w), H2AT(xv.w), a3);
        b0 = __hfma2(H2AT(v.x), H2AT(xv.x), b0);
        b1 = __hfma2(H2AT(v.y), H2AT(xv.y), b1);
        b2 = __hfma2(H2AT(v.z), H2AT(xv.z), b2);
        b3 = __hfma2(H2AT(v.w), H2AT(xv.w), b3);
        c0 = __hfma2(H2AT(w.x), H2AT(xv.x), c0);
        c1 = __hfma2(H2AT(w.y), H2AT(xv.y), c1);
        c2 = __hfma2(H2AT(w.z), H2AT(xv.z), c2);
        c3 = __hfma2(H2AT(w.w), H2AT(xv.w), c3);
    }
    if (REM > 0 && lane < REM) {
        int c = KF * 32 + lane;
        uint4 u = A[c], v = B[c], w = Cc[c], xv = xs[c];
        a0 = __hfma2(H2AT(u.x), H2AT(xv.x), a0);
        a1 = __hfma2(H2AT(u.y), H2AT(xv.y), a1);
        a2 = __hfma2(H2AT(u.z), H2AT(xv.z), a2);
        a3 = __hfma2(H2AT(u.w), H2AT(xv.w), a3);
        b0 = __hfma2(H2AT(v.x), H2AT(xv.x), b0);
        b1 = __hfma2(H2AT(v.y), H2AT(xv.y), b1);
        b2 = __hfma2(H2AT(v.z), H2AT(xv.z), b2);
        b3 = __hfma2(H2AT(v.w), H2AT(xv.w), b3);
        c0 = __hfma2(H2AT(w.x), H2AT(xv.x), c0);
        c1 = __hfma2(H2AT(w.y), H2AT(xv.y), c1);
        c2 = __hfma2(H2AT(w.z), H2AT(xv.z), c2);
        c3 = __hfma2(H2AT(w.w), H2AT(xv.w), c3);
    }
    float2 fa0 = __half22float2(a0), fa1 = __half22float2(a1);
    float2 fa2 = __half22float2(a2), fa3 = __half22float2(a3);
    float2 fb0 = __half22float2(b0), fb1 = __half22float2(b1);
    float2 fb2 = __half22float2(b2), fb3 = __half22float2(b3);
    float2 fc0 = __half22float2(c0), fc1 = __half22float2(c1);
    float2 fc2 = __half22float2(c2), fc3 = __half22float2(c3);
    float ra = ((fa0.x + fa0.y) + (fa1.x + fa1.y)) + ((fa2.x + fa2.y) + (fa3.x + fa3.y));
    float rb = ((fb0.x + fb0.y) + (fb1.x + fb1.y)) + ((fb2.x + fb2.y) + (fb3.x + fb3.y));
    float rc = ((fc0.x + fc0.y) + (fc1.x + fc1.y)) + ((fc2.x + fc2.y) + (fc3.x + fc3.y));
#pragma unroll
    for (int o = 16; o; o >>= 1) {
        ra += __shfl_down_sync(0xffffffffu, ra, o);
        rb += __shfl_down_sync(0xffffffffu, rb, o);
        rc += __shfl_down_sync(0xffffffffu, rc, o);
    }
    return make_float3(ra, rb, rc);
}

// single row, depth-8 register ring
template <int N8>
__device__ __forceinline__ float dot_pipe(const __half* __restrict__ w,
                                          const uint4* __restrict__ xs) {
    constexpr int KF  = N8 / 32;
    constexpr int REM = N8 - KF * 32;
    constexpr int D   = 8;
    const uint4* W = (const uint4*)w;
    const int lane = threadIdx.x & 31;
    uint4 bufW[D], bufX[D];
#pragma unroll
    for (int s = 0; s < D; ++s) {
        if (s < KF) {
            int c = s * 32 + lane;
            bufW[s] = W[c]; bufX[s] = xs[c];
        }
    }
    __half2 z = __float2half2_rn(0.f);
    __half2 a0 = z, a1 = z, a2 = z, a3 = z;
#pragma unroll
    for (int k = 0; k < KF; ++k) {
        const int sl = k % D;
        uint4 wv = bufW[sl], xv = bufX[sl];
        const int kn = k + D;
        if (kn < KF) {
            int c = kn * 32 + lane;
            bufW[sl] = W[c]; bufX[sl] = xs[c];
        }
        a0 = __hfma2(H2AT(wv.x), H2AT(xv.x), a0);
        a1 = __hfma2(H2AT(wv.y), H2AT(xv.y), a1);
        a2 = __hfma2(H2AT(wv.z), H2AT(xv.z), a2);
        a3 = __hfma2(H2AT(wv.w), H2AT(xv.w), a3);
    }
    if (REM > 0 && lane < REM) {
        int c = KF * 32 + lane;
        uint4 wv = W[c], xv = xs[c];
        a0 = __hfma2(H2AT(wv.x), H2AT(xv.x), a0);
        a1 = __hfma2(H2AT(wv.y), H2AT(xv.y), a1);
        a2 = __hfma2(H2AT(wv.z), H2AT(xv.z), a2);
        a3 = __hfma2(H2AT(wv.w), H2AT(xv.w), a3);
    }
    float2 f0 = __half22float2(a0), f1 = __half22float2(a1);
    float2 f2 = __half22float2(a2), f3 = __half22float2(a3);
    float acc = ((f0.x + f0.y) + (f1.x + f1.y)) + ((f2.x + f2.y) + (f3.x + f3.y));
#pragma unroll
    for (int o = 16; o; o >>= 1) acc += __shfl_down_sync(0xffffffffu, acc, o);
    return acc;
}

// fp32 row dot over H2 (W3)
__device__ __forceinline__ float warp_dot_f(const float* __restrict__ w,
                                            const float* __restrict__ x) {
    const float4* w4 = (const float4*)w;
    const float4* x4 = (const float4*)x;
    int lane = threadIdx.x & 31;
    float a0 = 0.f, a1 = 0.f, a2 = 0.f, a3 = 0.f;
#pragma unroll
    for (int c = lane; c < H2_ / 4; c += 32) {
        float4 a = w4[c], b = x4[c];
        a0 = fmaf(a.x, b.x, a0); a1 = fmaf(a.y, b.y, a1);
        a2 = fmaf(a.z, b.z, a2); a3 = fmaf(a.w, b.w, a3);
    }
    float acc = (a0 + a1) + (a2 + a3);
#pragma unroll
    for (int o = 16; o; o >>= 1) acc += __shfl_down_sync(0xffffffffu, acc, o);
    return acc;
}

__device__ __forceinline__ float sigmoidf_(float x) {
    return 1.f / (1.f + __expf(-x));
}

// ---------------- persistent kernel ----------------
__global__ void __launch_bounds__(NTHR, 1)
kalmannet_kernel(const float* __restrict__ A,   const float* __restrict__ C,
                 const float* __restrict__ x0,  const float* __restrict__ h0,
                 const float* __restrict__ y,   const float* __restrict__ W1,
                 const float* __restrict__ b1,  const float* __restrict__ bih,
                 const float* __restrict__ bhh, const float* __restrict__ b2,
                 const float* __restrict__ W3,  const float* __restrict__ b3,
                 float* __restrict__ out) {
    const int tid  = threadIdx.x;
    const int bid  = blockIdx.x;
    const int wid  = tid >> 5;
    const int lane = tid & 31;

    __shared__ __align__(16) uint4 s_x[H1_ / 8];
    __shared__ __align__(16) float s_l2f[H2_];
    __shared__ __align__(16) float s_z[DOUT];
    __shared__ __align__(16) float s_knet[56];
    __shared__ __align__(16) float s_gi3[NWARP][4];
    __shared__ float s_dy[N_];
    __shared__ float s_xprior[M_], s_xpost[M_], s_xprev[M_];

    for (int t = 0; t < T_LEN; ++t) {
        // ---------- stage h(t-1) as half2 ----------
        if ((bid >= W2_LO && bid <= W2_HI && t > 0) || bid >= WHH_LO) {
            if (t == 0) {
                for (int i = tid; i < HID_ / 2; i += NTHR) {
                    float2 f = ((const float2*)h0)[i];
                    ((__half2*)s_x)[i] = __floats2half2_rn(f.x, f.y);
                }
            } else {
                const uint4* src = (const uint4*)g_hh2;
                for (int i = tid; i < HID_ / 8; i += NTHR) s_x[i] = src[i];
            }
            __syncthreads();
        }

        // ---------- W2: l2(t-1) ----------
        if (bid >= W2_LO && bid <= W2_HI && t > 0) {
            int r = (bid - W2_LO) + 48 * wid;
            float v = dot_pipe<HID_ / 8>(w2H + (size_t)r * HID_, s_x);
            if (lane == 0) g_l2[r] = fmaxf(v + b2[r], 0.f);
            signal_done(&g_l2done);
        }

        // ---------- W3: z(t-1) ----------
        if (bid >= W3_LO && bid <= W3_HI && t > 0) {
            wait_ctr(&g_l2done, 48u * (unsigned)t);
            for (int i = tid; i < H2_; i += NTHR) s_l2f[i] = g_l2[i];
            __syncthreads();
            if (wid < 12) {
                int r = (bid - W3_LO) + 16 * wid;
                float v = warp_dot_f(W3 + (size_t)r * H2_, s_l2f);
                if (lane == 0) g_z[r] = (v + b3[r]) * 1e-4f;
            }
            signal_done(&g_zdone);
        }

        // ---------- block 0: serial chain -> knet ----------
        if (bid == 0) {
            if (t == 0) {
                if (tid < M_) { s_xpost[tid] = x0[tid]; s_xprev[tid] = x0[tid]; }
                __syncthreads();
            } else {
                wait_ctr(&g_zdone, 16u * (unsigned)t);
                if (tid < DOUT) s_z[tid] = g_z[tid];
                __syncthreads();
                if (tid < M_) {
                    float acc = 0.f;
#pragma unroll 4
                    for (int j = 0; j < N_; ++j)
                        acc = fmaf(s_z[tid * N_ + j], s_dy[j], acc);
                    float xp = s_xprior[tid] + acc;
                    s_xprev[tid] = s_xprior[tid];
                    s_xpost[tid] = xp;
                    out[tid * T_LEN + (t - 1)] = xp;
                }
                __syncthreads();
            }
            if (tid < M_) {
                float acc = 0.f;
#pragma unroll
                for (int k = 0; k < M_; ++k) acc = fmaf(A[tid * M_ + k], s_xpost[k], acc);
                s_xprior[tid] = acc;
            }
            __syncthreads();
            if (wid == 0) {
                for (int j = lane; j < N_; j += 32) {
                    float m = C[j * (M_ + 1) + M_];
#pragma unroll
                    for (int k = 0; k < M_; ++k) m = fmaf(C[j * (M_ + 1) + k], s_xprior[k], m);
                    s_dy[j] = y[j * T_LEN + t] - m;
                }
                __syncwarp();
                float sq = 0.f;
                for (int j = lane; j < N_; j += 32) sq += s_dy[j] * s_dy[j];
#pragma unroll
                for (int o = 16; o; o >>= 1) sq += __shfl_down_sync(0xffffffffu, sq, o);
                sq = __shfl_sync(0xffffffffu, sq, 0);
                float inv = 1.f / fmaxf(sqrtf(sq), 1e-12f);
                for (int j = lane; j < N_; j += 32) g_knet[j] = s_dy[j] * inv;

                float dx = (lane < M_) ? (s_xpost[lane] - s_xprev[lane]) : 0.f;
                float sq2 = dx * dx;
#pragma unroll
                for (int o = 16; o; o >>= 1) sq2 += __shfl_down_sync(0xffffffffu, sq2, o);
                sq2 = __shfl_sync(0xffffffffu, sq2, 0);
                float inv2 = 1.f / fmaxf(sqrtf(sq2), 1e-12f);
                if (lane < M_) g_knet[N_ + lane] = dx * inv2;
                __syncwarp();
                if (lane == 0) {
                    __threadfence();
                    *((volatile unsigned*)&g_knetflag) = (unsigned)(t + 1);
                }
            }
        }

        // ---------- W1 blocks: l1 ----------
        if (bid >= W1_LO && bid <= W1_HI) {
            if (tid == 0) {
                while (*((volatile unsigned*)&g_knetflag) < (unsigned)(t + 1)) { }
                __threadfence();
            }
            __syncthreads();
            if (tid < DIN) s_knet[tid] = g_knet[tid];
            __syncthreads();
            int base = (bid - W1_LO) * 520;
#pragma unroll
            for (int q = 0; q < 2; ++q) {
                int idx = q * NTHR + tid;
                if (idx < 520) {
                    int r = base + idx;
                    const float4* w4 = (const float4*)(W1 + (size_t)r * DIN);
                    const float4* k4 = (const float4*)s_knet;
                    float acc = b1[r];
#pragma unroll
                    for (int c = 0; c < DIN / 4; ++c) {
                        float4 a = w4[c], b = k4[c];
                        acc = fmaf(a.x, b.x, acc); acc = fmaf(a.y, b.y, acc);
                        acc = fmaf(a.z, b.z, acc); acc = fmaf(a.w, b.w, acc);
                    }
                    g_l1h[r] = __float2half(fmaxf(acc, 0.f));
                }
            }
            signal_done(&g_l1done);
        }

        // ---------- Whh blocks: gh rows ----------
        if (bid >= WHH_LO) {
            int gw = (bid - WHH_LO) * NWARP + wid;
#pragma unroll
            for (int q = 0; q < 2; ++q) {
                int u = gw + q * WHH_WARPS;
                if (u < HID_) {
                    float3 g = dot3_pipe<HID_ / 8>(w_hhH + (size_t)u * HID_,
                                                   w_hhH + (size_t)(u + HID_) * HID_,
                                                   w_hhH + (size_t)(u + 2 * HID_) * HID_,
                                                   s_x);
                    if (lane == 0) {
                        g_gh[u]            = g.x + bhh[u];
                        g_gh[u + HID_]     = g.y + bhh[u + HID_];
                        g_gh[u + 2 * HID_] = g.z + bhh[u + 2 * HID_];
                    }
                }
            }
            signal_done(&g_ghdone);
        }

        // ---------- all blocks: gi + gate ----------
        wait_ctr(&g_l1done, 8u * (unsigned)(t + 1));
        {
            const uint4* src = (const uint4*)g_l1h;
            for (int i = tid; i < H1_ / 8; i += NTHR) s_x[i] = src[i];
        }
        __syncthreads();
        {
            int u = bid + NBLK * wid;
            if (u < HID_) {
                float3 g = dot3_pipe<H1_ / 8>(w_ihH + (size_t)u * H1_,
                                              w_ihH + (size_t)(u + HID_) * H1_,
                                              w_ihH + (size_t)(u + 2 * HID_) * H1_,
                                              s_x);
                if (lane == 0) {
                    s_gi3[wid][0] = g.x + bih[u];
                    s_gi3[wid][1] = g.y + bih[u + HID_];
                    s_gi3[wid][2] = g.z + bih[u + 2 * HID_];
                }
            }
        }
        wait_ctr(&g_ghdone, (unsigned)WHH_NB * (unsigned)(t + 1));
        if (tid < NWARP) {
            int u = bid + NBLK * tid;
            if (u < HID_) {
                float hold = (t == 0) ? h0[u] : g_hf[u];
                float rg = sigmoidf_(s_gi3[tid][0] + g_gh[u]);
                float zg = sigmoidf_(s_gi3[tid][1] + g_gh[u + HID_]);
                float ng = tanhf(s_gi3[tid][2] + rg * g_gh[u + 2 * HID_]);
                float hv = (1.f - zg) * ng + zg * hold;
                g_hf[u]  = hv;
                g_hh2[u] = __float2half(hv);
            }
        }
        grid_barrier();
    }

    // ================= epilogue: x_post(T-1) =================
    if (bid >= W2_LO && bid <= W2_HI) {
        const uint4* src = (const uint4*)g_hh2;
        for (int i = tid; i < HID_ / 8; i += NTHR) s_x[i] = src[i];
        __syncthreads();
        int r = (bid - W2_LO) + 48 * wid;
        float v = dot_pipe<HID_ / 8>(w2H + (size_t)r * HID_, s_x);
        if (lane == 0) g_l2[r] = fmaxf(v + b2[r], 0.f);
        signal_done(&g_l2done);
    }
    if (bid >= W3_LO && bid <= W3_HI) {
        wait_ctr(&g_l2done, 48u * (unsigned)T_LEN);
        for (int i = tid; i < H2_; i += NTHR) s_l2f[i] = g_l2[i];
        __syncthreads();
        if (wid < 12) {
            int r = (bid - W3_LO) + 16 * wid;
            float v = warp_dot_f(W3 + (size_t)r * H2_, s_l2f);
            if (lane == 0) g_z[r] = (v + b3[r]) * 1e-4f;
        }
        signal_done(&g_zdone);
    }
    if (bid == 0) {
        wait_ctr(&g_zdone, 16u * (unsigned)T_LEN);
        if (tid < DOUT) s_z[tid] = g_z[tid];
        __syncthreads();
        if (tid < M_) {
            float acc = 0.f;
#pragma unroll 4
            for (int j = 0; j < N_; ++j) acc = fmaf(s_z[tid * N_ + j], s_dy[j], acc);
            out[tid * T_LEN + (T_LEN - 1)] = s_xprior[tid] + acc;
        }
        __syncthreads();
        if (tid == 0) {
            __threadfence();
            *((volatile unsigned*)&g_l2done)   = 0u;
            *((volatile unsigned*)&g_zdone)    = 0u;
            *((volatile unsigned*)&g_knetflag) = 0u;
            *((volatile unsigned*)&g_l1done)   = 0u;
            *((volatile unsigned*)&g_ghdone)   = 0u;
            *((volatile unsigned*)&g_bar_count) = 0u;
            *((volatile unsigned*)&g_bar_gen)   = 0u;
            __threadfence();
        }
    }
}

// ---------------- launch ----------------
extern "C" void kernel_launch(void* const* d_in, const int* in_sizes, int n_in,
                              void* d_out, int out_size) {
    const float* A    = (const float*)d_in[0];
    const float* C    = (const float*)d_in[1];
    const float* x0   = (const float*)d_in[2];
    const float* h0   = (const float*)d_in[3];
    const float* y    = (const float*)d_in[4];
    const float* W1   = (const float*)d_in[5];
    const float* b1   = (const float*)d_in[6];
    const float* Wih  = (const float*)d_in[7];
    const float* Whh  = (const float*)d_in[8];
    const float* bih  = (const float*)d_in[9];
    const float* bhh  = (const float*)d_in[10];
    const float* W2   = (const float*)d_in[11];
    const float* b2   = (const float*)d_in[12];
    const float* W3   = (const float*)d_in[13];
    const float* b3   = (const float*)d_in[14];
    float* out = (float*)d_out;

    cvt_kernel<<<2048, 256>>>(Wih, Whh, W2);
    kalmannet_kernel<<<NBLK, NTHR>>>(A, C, x0, h0, y, W1, b1, bih, bhh,
                                     b2, W3, b3, out);
}